// round 2
// baseline (speedup 1.0000x reference)
#include <cuda_runtime.h>

// Problem constants (fixed by the reference)
#define N_NODES 100000
#define N_EDGES 50000
#define M_INC   1600000
#define D       64
#define D2      (D / 2)   // float2 chunks per row; one warp covers a row

// ---------------------------------------------------------------------------
// Scratch (__device__ globals; allocation-free rule)
// ---------------------------------------------------------------------------
__device__ int   g_ecnt[N_EDGES];        // edge cardinality (== Be counts)
__device__ int   g_eoff[N_EDGES + 1];    // CSR offsets, edge -> member nodes
__device__ int   g_ecur[N_EDGES];        // scatter cursors
__device__ int   g_ncnt[N_NODES];
__device__ int   g_noff[N_NODES + 1];    // CSR offsets, node -> incident edges
__device__ int   g_ncur[N_NODES];
__device__ float g_Dn[N_NODES];          // weighted node degree
__device__ int   g_emem[M_INC];          // node ids grouped by edge
__device__ int   g_nmem[M_INC];          // edge ids grouped by node
__device__ float g_ef[(long)N_EDGES * D];// edge features (stage-1 output)

// ---------------------------------------------------------------------------
// K0: zero the small count/degree arrays (big arrays are fully overwritten)
// ---------------------------------------------------------------------------
__global__ void k_zero() {
    int i = blockIdx.x * blockDim.x + threadIdx.x;
    int stride = gridDim.x * blockDim.x;
    for (int j = i; j < N_EDGES; j += stride) g_ecnt[j] = 0;
    for (int j = i; j < N_NODES; j += stride) { g_ncnt[j] = 0; g_Dn[j] = 0.f; }
}

// ---------------------------------------------------------------------------
// K1: histogram both directions + weighted node degree
// ---------------------------------------------------------------------------
__global__ void k_hist(const int* __restrict__ ni, const int* __restrict__ ei,
                       const float* __restrict__ w) {
    int m = blockIdx.x * blockDim.x + threadIdx.x;
    if (m >= M_INC) return;
    int n = ni[m];
    int e = ei[m];
    atomicAdd(&g_ecnt[e], 1);
    atomicAdd(&g_ncnt[n], 1);
    atomicAdd(&g_Dn[n], __ldg(&w[e]));
}

// ---------------------------------------------------------------------------
// K2: exclusive scans (block 0: edges, block 1: nodes). 1024 threads/block.
// ---------------------------------------------------------------------------
__global__ void k_scan() {
    const int* cnt; int* off; int* cur; int len;
    if (blockIdx.x == 0) { cnt = g_ecnt; off = g_eoff; cur = g_ecur; len = N_EDGES; }
    else                 { cnt = g_ncnt; off = g_noff; cur = g_ncur; len = N_NODES; }

    int t = threadIdx.x;
    int chunk = (len + 1023) >> 10;
    int beg = t * chunk;
    int end = min(beg + chunk, len);

    int s = 0;
    for (int i = beg; i < end; i++) s += cnt[i];

    __shared__ int sh[1024];
    sh[t] = s;
    __syncthreads();
    // Hillis–Steele inclusive scan over thread sums
    for (int d = 1; d < 1024; d <<= 1) {
        int add = (t >= d) ? sh[t - d] : 0;
        __syncthreads();
        sh[t] += add;
        __syncthreads();
    }
    int run = sh[t] - s;   // exclusive prefix of this thread's range

    for (int i = beg; i < end; i++) {
        off[i] = run;
        cur[i] = run;
        run += cnt[i];
    }
    if (beg < len && end == len) off[len] = run;  // unique closing thread
}

// ---------------------------------------------------------------------------
// K3: scatter incidences into both CSR member lists
// ---------------------------------------------------------------------------
__global__ void k_scatter(const int* __restrict__ ni, const int* __restrict__ ei) {
    int m = blockIdx.x * blockDim.x + threadIdx.x;
    if (m >= M_INC) return;
    int n = ni[m];
    int e = ei[m];
    int p = atomicAdd(&g_ecur[e], 1);
    g_emem[p] = n;
    int q = atomicAdd(&g_ncur[n], 1);
    g_nmem[q] = e;
}

// ---------------------------------------------------------------------------
// K4: stage 1 — warp per edge: ef[e] = (1/deg) * sum_{n in e} x[n]
// Lane owns 2 consecutive floats (float2). Index loads amortized via shfl.
// ---------------------------------------------------------------------------
__global__ void k_stage1(const float* __restrict__ x) {
    int warp = (blockIdx.x * blockDim.x + threadIdx.x) >> 5;
    int lane = threadIdx.x & 31;
    if (warp >= N_EDGES) return;

    int beg = g_eoff[warp];
    int end = g_eoff[warp + 1];

    float ax = 0.f, ay = 0.f;
    const float2* x2 = (const float2*)x;

    int base = beg;
    for (; base + 32 <= end; base += 32) {
        int idx = g_emem[base + lane];
        #pragma unroll
        for (int j = 0; j < 32; j++) {
            int n = __shfl_sync(0xffffffffu, idx, j);
            float2 v = x2[(long)n * D2 + lane];
            ax += v.x; ay += v.y;
        }
    }
    if (base < end) {
        int rem = end - base;
        int idx = (lane < rem) ? g_emem[base + lane] : 0;
        for (int j = 0; j < rem; j++) {
            int n = __shfl_sync(0xffffffffu, idx, j);
            float2 v = x2[(long)n * D2 + lane];
            ax += v.x; ay += v.y;
        }
    }

    int deg = end - beg;
    float ber = (deg > 0) ? (1.0f / (float)deg) : 0.f;  // Be reciprocal
    ((float2*)g_ef)[(long)warp * D2 + lane] = make_float2(ax * ber, ay * ber);
}

// ---------------------------------------------------------------------------
// K5: stage 2 — warp per node: out[n] = 0.5*(x[n] + Dnr[n]*sum_{e ∋ n} ef[e])
// ---------------------------------------------------------------------------
__global__ void k_stage2(const float* __restrict__ x, float* __restrict__ out) {
    int warp = (blockIdx.x * blockDim.x + threadIdx.x) >> 5;
    int lane = threadIdx.x & 31;
    if (warp >= N_NODES) return;

    int beg = g_noff[warp];
    int end = g_noff[warp + 1];

    float ax = 0.f, ay = 0.f;
    const float2* ef2 = (const float2*)g_ef;

    int base = beg;
    for (; base + 32 <= end; base += 32) {
        int idx = g_nmem[base + lane];
        #pragma unroll
        for (int j = 0; j < 32; j++) {
            int e = __shfl_sync(0xffffffffu, idx, j);
            float2 v = ef2[(long)e * D2 + lane];
            ax += v.x; ay += v.y;
        }
    }
    if (base < end) {
        int rem = end - base;
        int idx = (lane < rem) ? g_nmem[base + lane] : 0;
        for (int j = 0; j < rem; j++) {
            int e = __shfl_sync(0xffffffffu, idx, j);
            float2 v = ef2[(long)e * D2 + lane];
            ax += v.x; ay += v.y;
        }
    }

    float dn = g_Dn[warp];
    float dnr = (dn > 0.f) ? (1.0f / dn) : 0.f;
    float2 xr = ((const float2*)x)[(long)warp * D2 + lane];
    float2 o;
    o.x = 0.5f * (xr.x + dnr * ax);
    o.y = 0.5f * (xr.y + dnr * ay);
    ((float2*)out)[(long)warp * D2 + lane] = o;
}

// ---------------------------------------------------------------------------
extern "C" void kernel_launch(void* const* d_in, const int* in_sizes, int n_in,
                              void* d_out, int out_size) {
    const float* x  = (const float*)d_in[0];
    const int*   ni = (const int*)d_in[1];
    const int*   ei = (const int*)d_in[2];
    const float* w  = (const float*)d_in[3];
    float* out = (float*)d_out;

    const int T = 256;
    const int mblocks = (M_INC + T - 1) / T;

    k_zero<<<256, T>>>();
    k_hist<<<mblocks, T>>>(ni, ei, w);
    k_scan<<<2, 1024>>>();
    k_scatter<<<mblocks, T>>>(ni, ei);

    // warp per segment: 32 threads per edge / node
    k_stage1<<<(N_EDGES * 32 + T - 1) / T, T>>>(x);
    k_stage2<<<(N_NODES * 32 + T - 1) / T, T>>>(x, out);
}